// round 3
// baseline (speedup 1.0000x reference)
#include <cuda_runtime.h>
#include <math.h>
#include <stdint.h>
#include <stddef.h>

// Problem constants (shapes fixed by the dataset)
#define NN   10000
#define EE   160000
#define HD   32      // hidden
#define NDD  64      // node_dim
#define EDD  16      // edge_dim
#define MHH  128     // edge mlp hidden

// ---------------- scratch (device globals; no allocation allowed) ----------
__device__ int   g_is64;
__device__ int   g_src[EE], g_dst[EE];
__device__ int   g_cnt_src[NN], g_cnt_dst[NN];
__device__ int   g_off_src[NN + 1], g_off_dst[NN + 1];
__device__ int   g_cur_src[NN], g_cur_dst[NN];
__device__ int   g_ebysrc[EE], g_ebydst[EE];
__device__ float g_h[NN * HD];
__device__ float g_z[(size_t)EE * MHH];          // relu(ea@W1+b1)      82 MB
__device__ float g_W2t[HD * MHH * HD];           // [j][i*128+m] = W2[m][i*32+j]
__device__ float g_b2t[HD * HD];                 // [j][i] = b2[i*32+j]
__device__ float g_P[(size_t)NN * MHH * HD];     // [n][i*128+m]       164 MB
__device__ float g_msg[(size_t)EE * HD];         // per-edge message    20 MB

// ---------------- small helpers -------------------------------------------

__device__ __forceinline__ void split_tf32(float v, uint32_t& hi, uint32_t& lo) {
    uint32_t h;
    asm("cvt.rna.tf32.f32 %0, %1;" : "=r"(h) : "f"(v));
    float lf = v - __uint_as_float(h);
    uint32_t l;
    asm("cvt.rna.tf32.f32 %0, %1;" : "=r"(l) : "f"(lf));
    hi = h; lo = l;
}

__device__ __forceinline__ void mma_tf32(float* c, const uint32_t* a, const uint32_t* b) {
    asm volatile(
        "mma.sync.aligned.m16n8k8.row.col.f32.tf32.tf32.f32 "
        "{%0,%1,%2,%3}, {%4,%5,%6,%7}, {%8,%9}, {%0,%1,%2,%3};"
        : "+f"(c[0]), "+f"(c[1]), "+f"(c[2]), "+f"(c[3])
        : "r"(a[0]), "r"(a[1]), "r"(a[2]), "r"(a[3]), "r"(b[0]), "r"(b[1]));
}

// ---------------- setup kernels -------------------------------------------

// Detect int64 vs int32 edge_index: int64 little-endian => every odd 32-bit
// word of the first 128 (src) entries is 0 (values in [0,10000)).
__global__ void k_detect(const int* __restrict__ w) {
    __shared__ int ok;
    if (threadIdx.x == 0) ok = 1;
    __syncthreads();
    if (w[2 * threadIdx.x + 1] != 0) atomicExch(&ok, 0);
    __syncthreads();
    if (threadIdx.x == 0) g_is64 = ok;
}

__global__ void k_zero_counts(int nN) {
    int i = blockIdx.x * 256 + threadIdx.x;
    if (i < nN) { g_cnt_src[i] = 0; g_cnt_dst[i] = 0; }
}

// Extract src/dst as int32 (branch on detected dtype) + degree histograms.
__global__ void k_extract(const int* __restrict__ w, int nE) {
    int e = blockIdx.x * 256 + threadIdx.x;
    if (e >= nE) return;
    int is64 = g_is64;
    int s, d;
    if (is64) { s = w[2 * e]; d = w[2 * (nE + e)]; }
    else      { s = w[e];     d = w[nE + e]; }
    g_src[e] = s; g_dst[e] = d;
    atomicAdd(&g_cnt_src[s], 1);
    atomicAdd(&g_cnt_dst[d], 1);
}

// Fast exclusive scan: per-thread sequential + warp/block shuffle scan.
// blockIdx 0 -> src arrays, 1 -> dst arrays.
__global__ __launch_bounds__(1024) void k_scan(int nN) {
    int* cnt = blockIdx.x ? g_cnt_dst : g_cnt_src;
    int* off = blockIdx.x ? g_off_dst : g_off_src;
    int* cur = blockIdx.x ? g_cur_dst : g_cur_src;
    const int CH = 10;                 // 1024*10 >= 10000
    int tid = threadIdx.x, lane = tid & 31, w = tid >> 5;
    int base = tid * CH;
    int v[CH];
    int s = 0;
#pragma unroll
    for (int q = 0; q < CH; q++) {
        int i = base + q;
        v[q] = (i < nN) ? cnt[i] : 0;
        s += v[q];
    }
    int sc = s;
#pragma unroll
    for (int o = 1; o < 32; o <<= 1) {
        int t = __shfl_up_sync(0xffffffffu, sc, o);
        if (lane >= o) sc += t;
    }
    __shared__ int wt[32];
    if (lane == 31) wt[w] = sc;
    __syncthreads();
    if (w == 0) {
        int t = wt[lane];
#pragma unroll
        for (int o = 1; o < 32; o <<= 1) {
            int u = __shfl_up_sync(0xffffffffu, t, o);
            if (lane >= o) t += u;
        }
        wt[lane] = t;
    }
    __syncthreads();
    int excl = sc - s + (w ? wt[w - 1] : 0);
    int run = excl;
#pragma unroll
    for (int q = 0; q < CH; q++) {
        int i = base + q;
        if (i < nN) { off[i] = run; cur[i] = run; run += v[q]; }
    }
    if (tid == 1023) off[nN] = excl + s;
}

__global__ void k_fill(int nE) {
    int e = blockIdx.x * 256 + threadIdx.x;
    if (e >= nE) return;
    int s = g_src[e], d = g_dst[e];
    int p = atomicAdd(&g_cur_src[s], 1); g_ebysrc[p] = e;
    int q = atomicAdd(&g_cur_dst[d], 1); g_ebydst[q] = e;
}

// W2t[j*4096 + i*128 + m] = W2[m*1024 + i*32 + j]  (msg-friendly permutation)
// b2t[j*32+i] = b2[i*32+j]
__global__ void k_w2t(const float* __restrict__ W2, const float* __restrict__ b2) {
    int t = blockIdx.x * 256 + threadIdx.x;
    if (t < HD * MHH * HD) {
        int j = t >> 12, i = (t >> 7) & 31, m = t & 127;
        g_W2t[t] = W2[m * 1024 + i * 32 + j];
    }
    int t2 = t - HD * MHH * HD;
    if (t2 >= 0 && t2 < HD * HD) {
        int j = t2 >> 5, i = t2 & 31;
        g_b2t[t2] = b2[i * 32 + j];
    }
}

// h0 = x @ Wp + bp   (warp per node)
__global__ __launch_bounds__(256) void k_h0(const float* __restrict__ x,
                                            const float* __restrict__ Wp,
                                            const float* __restrict__ bp, int nN) {
    __shared__ float Ws[NDD * HD];
    __shared__ float bs[HD];
    int tid = threadIdx.x;
    for (int i = tid; i < NDD * HD; i += 256) Ws[i] = Wp[i];
    if (tid < HD) bs[tid] = bp[tid];
    __syncthreads();
    int w = tid >> 5, lane = tid & 31;
    int n = blockIdx.x * 8 + w;
    if (n >= nN) return;
    float x0 = x[n * 64 + lane], x1 = x[n * 64 + 32 + lane];
    float acc = bs[lane];
#pragma unroll
    for (int j = 0; j < 32; j++) acc += __shfl_sync(0xffffffffu, x0, j) * Ws[j * 32 + lane];
#pragma unroll
    for (int j = 0; j < 32; j++) acc += __shfl_sync(0xffffffffu, x1, j) * Ws[(32 + j) * 32 + lane];
    g_h[n * 32 + lane] = acc;
}

// z = relu(ea @ W1 + b1)   (warp per edge)
__global__ __launch_bounds__(256) void k_z(const float* __restrict__ ea,
                                           const float* __restrict__ W1,
                                           const float* __restrict__ b1, int nE) {
    __shared__ float Ws[EDD * MHH];
    __shared__ float bs[MHH];
    int tid = threadIdx.x;
    for (int i = tid; i < EDD * MHH; i += 256) Ws[i] = W1[i];
    if (tid < MHH) bs[tid] = b1[tid];
    __syncthreads();
    int w = tid >> 5, lane = tid & 31;
    int e = blockIdx.x * 8 + w;
    if (e >= nE) return;
    float a0 = (lane < 16) ? ea[e * 16 + lane] : 0.f;
    float acc0 = bs[lane], acc1 = bs[32 + lane], acc2 = bs[64 + lane], acc3 = bs[96 + lane];
#pragma unroll
    for (int j = 0; j < 16; j++) {
        float a = __shfl_sync(0xffffffffu, a0, j);
        acc0 += a * Ws[j * 128 + lane];
        acc1 += a * Ws[j * 128 + 32 + lane];
        acc2 += a * Ws[j * 128 + 64 + lane];
        acc3 += a * Ws[j * 128 + 96 + lane];
    }
    float* zp = &g_z[(size_t)e * 128];
    zp[lane]      = fmaxf(acc0, 0.f);
    zp[32 + lane] = fmaxf(acc1, 0.f);
    zp[64 + lane] = fmaxf(acc2, 0.f);
    zp[96 + lane] = fmaxf(acc3, 0.f);
}

// ---------------- per-step kernels ----------------------------------------

// P = H (nN x 32) @ W2t (32 x 4096) with tensor cores, 3xTF32 split for
// fp32-level precision. Block tile 128x128, 8 warps in 2x4 grid, each warp
// 64x32 via mma.m16n8k8. Output layout per node: [i*128+m] (already permuted
// via W2t's layout) so k_msg stages it conflict-free.
__global__ __launch_bounds__(256) void k_P(int nN) {
    __shared__ float As[128][36];   // [row][k], pad 36: conflict-free frag loads
    __shared__ float Bs[32][136];   // [k][col], pad 136: conflict-free frag loads
    int tid = threadIdx.x;
    int bm = blockIdx.y * 128, bn = blockIdx.x * 128;
    for (int idx = tid; idx < 128 * 32; idx += 256) {
        int r = idx >> 5, k = idx & 31;
        int n = bm + r;
        As[r][k] = (n < nN) ? g_h[n * 32 + k] : 0.f;
    }
    for (int idx = tid; idx < 32 * 128; idx += 256) {
        int k = idx >> 7, c = idx & 127;
        Bs[k][c] = g_W2t[k * 4096 + bn + c];
    }
    __syncthreads();

    int warp = tid >> 5, lane = tid & 31;
    int g = lane >> 2, tg = lane & 3;
    int wm = (warp >> 2) * 64, wn = (warp & 3) * 32;

    float acc[4][4][4] = {};
#pragma unroll
    for (int k0 = 0; k0 < 32; k0 += 8) {
        uint32_t ah[4][4], al[4][4];
#pragma unroll
        for (int mf = 0; mf < 4; mf++) {
            int r = wm + mf * 16 + g;
            split_tf32(As[r][k0 + tg],         ah[mf][0], al[mf][0]);
            split_tf32(As[r + 8][k0 + tg],     ah[mf][1], al[mf][1]);
            split_tf32(As[r][k0 + tg + 4],     ah[mf][2], al[mf][2]);
            split_tf32(As[r + 8][k0 + tg + 4], ah[mf][3], al[mf][3]);
        }
        uint32_t bh[4][2], bl[4][2];
#pragma unroll
        for (int nf = 0; nf < 4; nf++) {
            int c = wn + nf * 8 + g;
            split_tf32(Bs[k0 + tg][c],     bh[nf][0], bl[nf][0]);
            split_tf32(Bs[k0 + tg + 4][c], bh[nf][1], bl[nf][1]);
        }
#pragma unroll
        for (int mf = 0; mf < 4; mf++)
#pragma unroll
            for (int nf = 0; nf < 4; nf++) {
                mma_tf32(acc[mf][nf], ah[mf], bh[nf]);
                mma_tf32(acc[mf][nf], ah[mf], bl[nf]);
                mma_tf32(acc[mf][nf], al[mf], bh[nf]);
            }
    }

#pragma unroll
    for (int mf = 0; mf < 4; mf++) {
        int r0 = bm + wm + mf * 16 + g;
#pragma unroll
        for (int nf = 0; nf < 4; nf++) {
            int c = bn + wn + nf * 8 + 2 * tg;
            if (r0 < nN)
                *(float2*)&g_P[(size_t)r0 * 4096 + c] = make_float2(acc[mf][nf][0], acc[mf][nf][1]);
            if (r0 + 8 < nN)
                *(float2*)&g_P[(size_t)(r0 + 8) * 4096 + c] = make_float2(acc[mf][nf][2], acc[mf][nf][3]);
        }
    }
}

// msg[e,i] = C[src,i] + sum_m z[e,m]*P[src,i,m]; block per src node, P row
// staged in smem once (conflict-free stride-132 float4 layout), reused across
// all that node's out-edges. C computed inline (32x32 GEMV).
__global__ __launch_bounds__(128) void k_msg() {
    int n = blockIdx.x;
    int off = g_off_src[n];
    int d = g_off_src[n + 1] - off;
    if (d == 0) return;
    __shared__ float Ps[32 * 132];       // [i][m], row stride 132 floats
    __shared__ float zb[4][4][128];
    __shared__ float Cn[32];
    int tid = threadIdx.x, w = tid >> 5, lane = tid & 31;
    const float4* Pg = (const float4*)&g_P[(size_t)n * 4096];
    for (int t = tid; t < 1024; t += 128) {
        int i = t >> 5, m4 = t & 31;
        *(float4*)&Ps[i * 132 + m4 * 4] = Pg[t];
    }
    if (tid < 32) {
        float acc = 0.f;
#pragma unroll
        for (int j = 0; j < 32; j++) acc += g_h[n * 32 + j] * g_b2t[j * 32 + tid];
        Cn[tid] = acc;
    }
    __syncthreads();

    for (int base = w * 4; base < d; base += 16) {
        int cnt = min(4, d - base);
        int eidx[4];
#pragma unroll
        for (int k = 0; k < 4; k++) {
            if (k < cnt) {
                int e = g_ebysrc[off + base + k];
                eidx[k] = e;
                const float4* zp4 = (const float4*)&g_z[(size_t)e * 128];
                *(float4*)&zb[w][k][lane * 4] = zp4[lane];
            }
        }
        __syncwarp();
        float acc[4];
#pragma unroll
        for (int k = 0; k < 4; k++) acc[k] = Cn[lane];
        const float4* prow = (const float4*)&Ps[lane * 132];
#pragma unroll 8
        for (int m4 = 0; m4 < 32; m4++) {
            float4 p = prow[m4];
#pragma unroll
            for (int k = 0; k < 4; k++) {
                float4 zv = *(const float4*)&zb[w][k][m4 * 4];
                acc[k] += p.x * zv.x + p.y * zv.y + p.z * zv.z + p.w * zv.w;
            }
        }
#pragma unroll
        for (int k = 0; k < 4; k++)
            if (k < cnt) g_msg[(size_t)eidx[k] * 32 + lane] = acc[k];
        __syncwarp();
    }
}

// Fused aggregation (dst-CSR gather) + GRUCell (torch layout [r,z,n]).
__global__ __launch_bounds__(256) void k_agg_gru(const float* __restrict__ wih,
                                                 const float* __restrict__ whh,
                                                 const float* __restrict__ bih,
                                                 const float* __restrict__ bhh,
                                                 float* __restrict__ out, int nN) {
    __shared__ float wi[32 * 96];   // wi[j*96+k] = wih[k*32+j]
    __shared__ float wh[32 * 96];
    __shared__ float bi[96], bh[96];
    int tid = threadIdx.x;
    for (int idx = tid; idx < 3072; idx += 256) {
        int k = idx >> 5, j = idx & 31;
        wi[j * 96 + k] = wih[idx];
        wh[j * 96 + k] = whh[idx];
    }
    if (tid < 96) { bi[tid] = bih[tid]; bh[tid] = bhh[tid]; }
    __syncthreads();
    int w = tid >> 5, lane = tid & 31;
    int n = blockIdx.x * 8 + w;
    if (n >= nN) return;

    int o = g_off_dst[n], d = g_off_dst[n + 1] - o;
    float av = 0.f;
    for (int k = 0; k < d; k++) {
        int e = g_ebydst[o + k];
        av += g_msg[(size_t)e * 32 + lane];
    }
    float hv = g_h[n * 32 + lane];

    float gi0 = bi[lane], gi1 = bi[32 + lane], gi2 = bi[64 + lane];
    float gh0 = bh[lane], gh1 = bh[32 + lane], gh2 = bh[64 + lane];
#pragma unroll
    for (int j = 0; j < 32; j++) {
        float a = __shfl_sync(0xffffffffu, av, j);
        float h = __shfl_sync(0xffffffffu, hv, j);
        gi0 += a * wi[j * 96 + lane];
        gi1 += a * wi[j * 96 + 32 + lane];
        gi2 += a * wi[j * 96 + 64 + lane];
        gh0 += h * wh[j * 96 + lane];
        gh1 += h * wh[j * 96 + 32 + lane];
        gh2 += h * wh[j * 96 + 64 + lane];
    }
    float r  = 1.f / (1.f + expf(-(gi0 + gh0)));
    float zz = 1.f / (1.f + expf(-(gi1 + gh1)));
    float nn = tanhf(gi2 + r * gh2);
    float hn = (1.f - zz) * nn + zz * hv;
    g_h[n * 32 + lane] = hn;
    out[n * 32 + lane] = hn;
}

// ---------------- launch ---------------------------------------------------

extern "C" void kernel_launch(void* const* d_in, const int* in_sizes, int n_in,
                              void* d_out, int out_size) {
    const float* x   = (const float*)d_in[0];
    const int*   ei  = (const int*)d_in[1];
    const float* ea  = (const float*)d_in[2];
    const float* Wp  = (const float*)d_in[3];
    const float* bp  = (const float*)d_in[4];
    const float* W1  = (const float*)d_in[5];
    const float* b1  = (const float*)d_in[6];
    const float* W2  = (const float*)d_in[7];
    const float* b2  = (const float*)d_in[8];
    const float* wih = (const float*)d_in[9];
    const float* whh = (const float*)d_in[10];
    const float* bih = (const float*)d_in[11];
    const float* bhh = (const float*)d_in[12];
    float* out = (float*)d_out;

    int nN = in_sizes[0] / NDD; if (nN > NN) nN = NN;
    int nE = in_sizes[2] / EDD; if (nE > EE) nE = EE;

    // ---- setup (per launch, deterministic) ----
    k_zero_counts<<<(nN + 255) / 256, 256>>>(nN);
    k_detect<<<1, 128>>>(ei);
    k_extract<<<(nE + 255) / 256, 256>>>(ei, nE);
    k_scan<<<2, 1024>>>(nN);
    k_fill<<<(nE + 255) / 256, 256>>>(nE);
    k_w2t<<<(HD * MHH * HD + HD * HD + 255) / 256, 256>>>(W2, b2);
    k_h0<<<(nN + 7) / 8, 256>>>(x, Wp, bp, nN);
    k_z<<<(nE + 7) / 8, 256>>>(ea, W1, b1, nE);

    // ---- 3 message-passing steps ----
    dim3 gP(32, (nN + 127) / 128);
    for (int step = 0; step < 3; step++) {
        k_P<<<gP, 256>>>(nN);
        k_msg<<<nN, 128>>>();
        k_agg_gru<<<(nN + 7) / 8, 256>>>(wih, whh, bih, bhh, out, nN);
    }
}